// round 2
// baseline (speedup 1.0000x reference)
#include <cuda_runtime.h>
#include <cstdint>

#define NNODES   8192
#define EMAX     131072
#define ESELMAX  (EMAX/2)
#define HID      768
#define MSG      249
#define MSGP     256
#define NDIM     3
#define INSHAPE  16
#define LND      19
#define LN_EPS   1e-5f

// -------- scratch (allocation-free rule: __device__ globals) --------
__device__ float g_h1[(size_t)ESELMAX * HID];     // layer1 out  [Esel, 768]
__device__ float g_h2[(size_t)ESELMAX * HID];     // layer2 out  [Esel, 768]
__device__ float g_w [(size_t)ESELMAX * MSGP];    // layer3 out  [Esel, 256] (padded)
__device__ float g_sea[ESELMAX * 6];              // compacted edge_attr
__device__ int   g_ssrc[ESELMAX];
__device__ int   g_sdst[ESELMAX];
__device__ float g_agg[NNODES * NDIM];
__device__ int   g_bcnt[1024];
__device__ int   g_boff[1024];
__device__ float g_w3p[HID * MSGP];               // mW3 padded to 256 cols
__device__ float g_b3p[MSGP];

__device__ __forceinline__ float leaky(float v) { return v > 0.f ? v : 0.01f * v; }

// -------- edge compaction: keep edges with src < dst (deterministic) --------
__global__ void k_count(const int* __restrict__ src, const int* __restrict__ dst, int E) {
    int e = blockIdx.x * blockDim.x + threadIdx.x;
    int pred = (e < E) && (src[e] < dst[e]);
    unsigned bal = __ballot_sync(0xffffffffu, pred);
    __shared__ int wc[32];
    int wid = threadIdx.x >> 5, lane = threadIdx.x & 31;
    if (lane == 0) wc[wid] = __popc(bal);
    __syncthreads();
    if (threadIdx.x == 0) {
        int nmw = blockDim.x >> 5, s = 0;
        for (int i = 0; i < nmw; i++) s += wc[i];
        g_bcnt[blockIdx.x] = s;
    }
}

__global__ void k_scan(int nb) {
    __shared__ int s[1024];
    int t = threadIdx.x;
    if (t < nb) s[t] = g_bcnt[t];
    __syncthreads();
    if (t == 0) {
        int acc = 0;
        for (int i = 0; i < nb; i++) { int v = s[i]; s[i] = acc; acc += v; }
    }
    __syncthreads();
    if (t < nb) g_boff[t] = s[t];
}

__global__ void k_scatter(const int* __restrict__ src, const int* __restrict__ dst,
                          const float* __restrict__ ea, int E) {
    int e = blockIdx.x * blockDim.x + threadIdx.x;
    int pred = (e < E) && (src[e] < dst[e]);
    unsigned bal = __ballot_sync(0xffffffffu, pred);
    __shared__ int wc[32], ws[32];
    int wid = threadIdx.x >> 5, lane = threadIdx.x & 31;
    if (lane == 0) wc[wid] = __popc(bal);
    __syncthreads();
    if (threadIdx.x == 0) {
        int nmw = blockDim.x >> 5, acc = 0;
        for (int i = 0; i < nmw; i++) { ws[i] = acc; acc += wc[i]; }
    }
    __syncthreads();
    if (pred) {
        int idx = g_boff[blockIdx.x] + ws[wid] + __popc(bal & ((1u << lane) - 1u));
        g_ssrc[idx] = src[e];
        g_sdst[idx] = dst[e];
        #pragma unroll
        for (int k = 0; k < 6; k++) g_sea[idx * 6 + k] = ea[(size_t)e * 6 + k];
    }
}

// -------- misc prep --------
__global__ void k_zero_agg() {
    int i = blockIdx.x * blockDim.x + threadIdx.x;
    if (i < NNODES * NDIM) g_agg[i] = 0.f;
}

__global__ void k_pad_w3(const float* __restrict__ W3, const float* __restrict__ b3) {
    int idx = blockIdx.x * blockDim.x + threadIdx.x;
    if (idx < HID * MSGP) {
        int r = idx / MSGP, c = idx - r * MSGP;
        g_w3p[idx] = (c < MSG) ? W3[r * MSG + c] : 0.f;
    }
    if (idx < MSGP) g_b3p[idx] = (idx < MSG) ? b3[idx] : 0.f;
}

// -------- layer1: [Esel,6] @ [6,768] + b, leaky; 8 edges per block --------
#define L1_EPB 8
__global__ void k_layer1(const float* __restrict__ W1, const float* __restrict__ b1, int esel) {
    int e0 = blockIdx.x * L1_EPB;
    __shared__ float ea[L1_EPB][6];
    int t = threadIdx.x;
    if (t < L1_EPB * 6) ea[t / 6][t % 6] = g_sea[e0 * 6 + t];
    __syncthreads();
    for (int n = t; n < HID; n += blockDim.x) {
        float w[6];
        #pragma unroll
        for (int k = 0; k < 6; k++) w[k] = W1[k * HID + n];
        float bb = b1[n];
        #pragma unroll
        for (int e = 0; e < L1_EPB; e++) {
            float acc = bb;
            #pragma unroll
            for (int k = 0; k < 6; k++) acc += ea[e][k] * w[k];
            g_h1[(size_t)(e0 + e) * HID + n] = leaky(acc);
        }
    }
}

// -------- tiled fp32 GEMM: C[M,N] = act(A[M,K] @ B[K,N] + bias) --------
// BM=BN=128, BK=16, 256 threads, 8x8 per thread. M%128==0, N%128==0, K%16==0.
__global__ void __launch_bounds__(256) k_gemm(const float* __restrict__ A,
                                              const float* __restrict__ B,
                                              const float* __restrict__ bias,
                                              float* __restrict__ C,
                                              int M, int N, int K, int act) {
    const int BM = 128, BN = 128, BK = 16;
    __shared__ float As[BK][BM];
    __shared__ float Bs[BK][BN];
    int tid = threadIdx.x;
    int m0 = blockIdx.y * BM;
    int n0 = blockIdx.x * BN;
    int tx = tid & 15, ty = tid >> 4;

    float acc[8][8];
    #pragma unroll
    for (int i = 0; i < 8; i++)
        #pragma unroll
        for (int j = 0; j < 8; j++) acc[i][j] = 0.f;

    int arow = tid >> 2;           // 0..63
    int acol = (tid & 3) * 4;      // 0,4,8,12
    int brow = tid >> 5;           // 0..7
    int bcol = (tid & 31) * 4;     // 0..124

    for (int k0 = 0; k0 < K; k0 += BK) {
        #pragma unroll
        for (int it = 0; it < 2; it++) {
            int r = arow + it * 64;
            float4 v = *(const float4*)(A + (size_t)(m0 + r) * K + k0 + acol);
            As[acol + 0][r] = v.x; As[acol + 1][r] = v.y;
            As[acol + 2][r] = v.z; As[acol + 3][r] = v.w;
        }
        #pragma unroll
        for (int it = 0; it < 2; it++) {
            int r = brow + it * 8;
            *(float4*)(&Bs[r][bcol]) = *(const float4*)(B + (size_t)(k0 + r) * N + n0 + bcol);
        }
        __syncthreads();
        #pragma unroll
        for (int k = 0; k < BK; k++) {
            float4 a0 = *(const float4*)&As[k][ty * 8];
            float4 a1 = *(const float4*)&As[k][ty * 8 + 4];
            float4 b0 = *(const float4*)&Bs[k][tx * 8];
            float4 b1 = *(const float4*)&Bs[k][tx * 8 + 4];
            float ra[8] = {a0.x, a0.y, a0.z, a0.w, a1.x, a1.y, a1.z, a1.w};
            float rb[8] = {b0.x, b0.y, b0.z, b0.w, b1.x, b1.y, b1.z, b1.w};
            #pragma unroll
            for (int i = 0; i < 8; i++)
                #pragma unroll
                for (int j = 0; j < 8; j++) acc[i][j] += ra[i] * rb[j];
        }
        __syncthreads();
    }

    #pragma unroll
    for (int i = 0; i < 8; i++) {
        int row = m0 + ty * 8 + i;
        #pragma unroll
        for (int j = 0; j < 8; j += 4) {
            int col = n0 + tx * 8 + j;
            float4 v;
            v.x = acc[i][j + 0] + bias[col + 0];
            v.y = acc[i][j + 1] + bias[col + 1];
            v.z = acc[i][j + 2] + bias[col + 2];
            v.w = acc[i][j + 3] + bias[col + 3];
            if (act) { v.x = leaky(v.x); v.y = leaky(v.y); v.z = leaky(v.z); v.w = leaky(v.w); }
            *(float4*)(C + (size_t)row * N + col) = v;
        }
    }
}

// -------- poly products + einsum + antisymmetric scatter (1 warp / edge) ----
__global__ void k_msg_scatter(int esel) {
    int gw = (blockIdx.x * blockDim.x + threadIdx.x) >> 5;
    int lane = threadIdx.x & 31;
    int wl = threadIdx.x >> 5;
    __shared__ float sprod[8][84];
    if (gw >= esel) return;

    if (lane == 0) {
        float ea[6];
        #pragma unroll
        for (int k = 0; k < 6; k++) ea[k] = g_sea[gw * 6 + k];
        int p = 0;
        #pragma unroll
        for (int a = 0; a < 6; a++) sprod[wl][p++] = ea[a];
        #pragma unroll
        for (int a = 0; a < 6; a++)
            for (int b = a; b < 6; b++) sprod[wl][p++] = ea[a] * ea[b];
        #pragma unroll
        for (int a = 0; a < 6; a++)
            for (int b = a; b < 6; b++)
                for (int c = b; c < 6; c++) sprod[wl][p++] = ea[a] * ea[b] * ea[c];
    }
    __syncwarp();

    float r0 = 0.f, r1 = 0.f, r2 = 0.f;
    const float* wrow = g_w + (size_t)gw * MSGP;
    for (int j = lane; j < MSG; j += 32) {
        int k = j / 83, p = j - k * 83;
        float t = wrow[j] * sprod[wl][p];
        if (k == 0) r0 += t; else if (k == 1) r1 += t; else r2 += t;
    }
    #pragma unroll
    for (int off = 16; off; off >>= 1) {
        r0 += __shfl_xor_sync(0xffffffffu, r0, off);
        r1 += __shfl_xor_sync(0xffffffffu, r1, off);
        r2 += __shfl_xor_sync(0xffffffffu, r2, off);
    }
    if (lane == 0) {
        int s = g_ssrc[gw], d = g_sdst[gw];
        atomicAdd(&g_agg[d * 3 + 0],  r0);
        atomicAdd(&g_agg[d * 3 + 1],  r1);
        atomicAdd(&g_agg[d * 3 + 2],  r2);
        atomicAdd(&g_agg[s * 3 + 0], -r0);
        atomicAdd(&g_agg[s * 3 + 1], -r1);
        atomicAdd(&g_agg[s * 3 + 2], -r2);
    }
}

// -------- node update: LN(19) + MLP 19->18->17->16 --------
__global__ void k_update(const float* __restrict__ x,
                         const float* __restrict__ ln_g, const float* __restrict__ ln_b,
                         const float* __restrict__ uW1, const float* __restrict__ ub1,
                         const float* __restrict__ uW2, const float* __restrict__ ub2,
                         const float* __restrict__ uW3, const float* __restrict__ ub3,
                         float* __restrict__ out) {
    __shared__ float sW1[19 * 18], sW2[18 * 17], sW3[17 * 16];
    __shared__ float sb1[18], sb2[17], sb3[16], sg[19], sbt[19];
    int t = threadIdx.x;
    for (int i = t; i < 19 * 18; i += blockDim.x) sW1[i] = uW1[i];
    for (int i = t; i < 18 * 17; i += blockDim.x) sW2[i] = uW2[i];
    for (int i = t; i < 17 * 16; i += blockDim.x) sW3[i] = uW3[i];
    if (t < 18) sb1[t] = ub1[t];
    if (t < 17) sb2[t] = ub2[t];
    if (t < 16) sb3[t] = ub3[t];
    if (t < 19) { sg[t] = ln_g[t]; sbt[t] = ln_b[t]; }
    __syncthreads();

    int node = blockIdx.x * blockDim.x + t;
    if (node >= NNODES) return;

    float h[19];
    #pragma unroll
    for (int i = 0; i < 16; i++) h[i] = x[node * 16 + i];
    #pragma unroll
    for (int k = 0; k < 3; k++) h[16 + k] = g_agg[node * 3 + k];

    float mu = 0.f;
    #pragma unroll
    for (int i = 0; i < 19; i++) mu += h[i];
    mu *= (1.f / 19.f);
    float var = 0.f;
    #pragma unroll
    for (int i = 0; i < 19; i++) { float dlt = h[i] - mu; var += dlt * dlt; }
    var *= (1.f / 19.f);
    float rs = rsqrtf(var + LN_EPS);
    float hn[19];
    #pragma unroll
    for (int i = 0; i < 19; i++) hn[i] = (h[i] - mu) * rs * sg[i] + sbt[i];

    float t1[18];
    #pragma unroll
    for (int j = 0; j < 18; j++) {
        float acc = sb1[j];
        #pragma unroll
        for (int i = 0; i < 19; i++) acc += hn[i] * sW1[i * 18 + j];
        t1[j] = leaky(acc);
    }
    float t2[17];
    #pragma unroll
    for (int j = 0; j < 17; j++) {
        float acc = sb2[j];
        #pragma unroll
        for (int i = 0; i < 18; i++) acc += t1[i] * sW2[i * 17 + j];
        t2[j] = leaky(acc);
    }
    #pragma unroll
    for (int j = 0; j < 16; j++) {
        float acc = sb3[j];
        #pragma unroll
        for (int i = 0; i < 17; i++) acc += t2[i] * sW3[i * 16 + j];
        out[node * 16 + j] = acc;
    }
}

// -------- launch --------
extern "C" void kernel_launch(void* const* d_in, const int* in_sizes, int n_in,
                              void* d_out, int out_size) {
    const float* x    = (const float*)d_in[0];
    const float* ea   = (const float*)d_in[1];
    const float* mW1  = (const float*)d_in[2];
    const float* mb1  = (const float*)d_in[3];
    const float* mW2  = (const float*)d_in[4];
    const float* mb2  = (const float*)d_in[5];
    const float* mW3  = (const float*)d_in[6];
    const float* mb3  = (const float*)d_in[7];
    const float* ln_g = (const float*)d_in[8];
    const float* ln_b = (const float*)d_in[9];
    const float* uW1  = (const float*)d_in[10];
    const float* ub1  = (const float*)d_in[11];
    const float* uW2  = (const float*)d_in[12];
    const float* ub2  = (const float*)d_in[13];
    const float* uW3  = (const float*)d_in[14];
    const float* ub3  = (const float*)d_in[15];
    const int*   eidx = (const int*)d_in[16];

    int E = in_sizes[1] / 6;               // 131072
    const int* src = eidx;
    const int* dst = eidx + E;
    int esel = E / 2;                      // 65536 (symmetric graph)
    int NB = (E + 1023) / 1024;

    float *p_h1, *p_h2, *p_w, *p_w3p, *p_b3p;
    cudaGetSymbolAddress((void**)&p_h1,  g_h1);
    cudaGetSymbolAddress((void**)&p_h2,  g_h2);
    cudaGetSymbolAddress((void**)&p_w,   g_w);
    cudaGetSymbolAddress((void**)&p_w3p, g_w3p);
    cudaGetSymbolAddress((void**)&p_b3p, g_b3p);

    k_zero_agg<<<(NNODES * NDIM + 255) / 256, 256>>>();
    k_count  <<<NB, 1024>>>(src, dst, E);
    k_scan   <<<1, 1024>>>(NB);
    k_scatter<<<NB, 1024>>>(src, dst, ea, E);
    k_pad_w3 <<<(HID * MSGP + 255) / 256, 256>>>(mW3, mb3);

    k_layer1 <<<esel / L1_EPB, 256>>>(mW1, mb1, esel);

    dim3 g2(HID / 128, esel / 128);
    k_gemm<<<g2, 256>>>(p_h1, mW2, mb2, p_h2, esel, HID, HID, 1);

    dim3 g3(MSGP / 128, esel / 128);
    k_gemm<<<g3, 256>>>(p_h2, p_w3p, p_b3p, p_w, esel, MSGP, HID, 0);

    k_msg_scatter<<<(esel * 32 + 255) / 256, 256>>>(esel);

    k_update<<<(NNODES + 127) / 128, 128>>>(x, ln_g, ln_b, uW1, ub1, uW2, ub2,
                                            uW3, ub3, (float*)d_out);
}

// round 4
// speedup vs baseline: 2.2987x; 2.2987x over previous
#include <cuda_runtime.h>
#include <cuda_bf16.h>
#include <cstdint>

#define NNODES   8192
#define EMAX     131072
#define ESEL     65536
#define HID      768
#define MSG      249
#define MSGP     256
#define LN_EPS   1e-5f

// ============================ PTX helpers (baseline, sm_80+) ============================
__device__ __forceinline__ uint32_t smem_to_u32(const void* p) {
    uint32_t a;
    asm("{ .reg .u64 t; cvta.to.shared.u64 t, %1; cvt.u32.u64 %0, t; }" : "=r"(a) : "l"(p));
    return a;
}
__device__ __forceinline__ void cp16(uint32_t s, const void* g) {
    asm volatile("cp.async.cg.shared.global [%0], [%1], 16;" :: "r"(s), "l"(g));
}
#define CP_COMMIT  asm volatile("cp.async.commit_group;" ::: "memory")
#define CP_WAIT1   asm volatile("cp.async.wait_group 1;" ::: "memory")
#define CP_WAIT0   asm volatile("cp.async.wait_group 0;" ::: "memory")

__device__ __forceinline__ void ldsm_x4(uint32_t* r, uint32_t addr) {
    asm volatile("ldmatrix.sync.aligned.m8n8.x4.shared.b16 {%0,%1,%2,%3}, [%4];"
        : "=r"(r[0]), "=r"(r[1]), "=r"(r[2]), "=r"(r[3]) : "r"(addr));
}
__device__ __forceinline__ void ldsm_x2(uint32_t* r, uint32_t addr) {
    asm volatile("ldmatrix.sync.aligned.m8n8.x2.shared.b16 {%0,%1}, [%2];"
        : "=r"(r[0]), "=r"(r[1]) : "r"(addr));
}
__device__ __forceinline__ void mma16816(float* d, const uint32_t* a, const uint32_t* b) {
    asm volatile("mma.sync.aligned.m16n8k16.row.col.f32.bf16.bf16.f32 "
        "{%0,%1,%2,%3}, {%4,%5,%6,%7}, {%8,%9}, {%0,%1,%2,%3};"
        : "+f"(d[0]), "+f"(d[1]), "+f"(d[2]), "+f"(d[3])
        : "r"(a[0]), "r"(a[1]), "r"(a[2]), "r"(a[3]), "r"(b[0]), "r"(b[1]));
}

// ============================ scratch ============================
__device__ __nv_bfloat16 g_h1hi[(size_t)ESEL * HID];
__device__ __nv_bfloat16 g_h1lo[(size_t)ESEL * HID];
__device__ __nv_bfloat16 g_h2hi[(size_t)ESEL * HID];
__device__ __nv_bfloat16 g_h2lo[(size_t)ESEL * HID];
__device__ __nv_bfloat16 g_w2thi[HID * HID];
__device__ __nv_bfloat16 g_w2tlo[HID * HID];
__device__ __nv_bfloat16 g_w3thi[MSGP * HID];
__device__ __nv_bfloat16 g_w3tlo[MSGP * HID];
__device__ float g_b3p[MSGP];
__device__ float g_w[(size_t)ESEL * MSGP];
__device__ float g_sea[ESEL * 6];
__device__ int   g_ssrc[ESEL];
__device__ int   g_sdst[ESEL];
__device__ float g_agg[NNODES * 3];
__device__ int   g_bcnt[1024];
__device__ int   g_boff[1024];

__device__ __forceinline__ float leaky(float v) { return v > 0.f ? v : 0.01f * v; }

// ============================ edge compaction (src < dst) ============================
__global__ void k_count(const int* __restrict__ src, const int* __restrict__ dst, int E) {
    int e = blockIdx.x * blockDim.x + threadIdx.x;
    int pred = (e < E) && (src[e] < dst[e]);
    unsigned bal = __ballot_sync(0xffffffffu, pred);
    __shared__ int wc[32];
    int wid = threadIdx.x >> 5, lane = threadIdx.x & 31;
    if (lane == 0) wc[wid] = __popc(bal);
    __syncthreads();
    if (threadIdx.x == 0) {
        int nmw = blockDim.x >> 5, s = 0;
        for (int i = 0; i < nmw; i++) s += wc[i];
        g_bcnt[blockIdx.x] = s;
    }
}
__global__ void k_scan(int nb) {
    __shared__ int s[1024];
    int t = threadIdx.x;
    if (t < nb) s[t] = g_bcnt[t];
    __syncthreads();
    if (t == 0) { int acc = 0; for (int i = 0; i < nb; i++) { int v = s[i]; s[i] = acc; acc += v; } }
    __syncthreads();
    if (t < nb) g_boff[t] = s[t];
}
__global__ void k_scatter(const int* __restrict__ src, const int* __restrict__ dst,
                          const float* __restrict__ ea, int E) {
    int e = blockIdx.x * blockDim.x + threadIdx.x;
    int pred = (e < E) && (src[e] < dst[e]);
    unsigned bal = __ballot_sync(0xffffffffu, pred);
    __shared__ int wc[32], ws[32];
    int wid = threadIdx.x >> 5, lane = threadIdx.x & 31;
    if (lane == 0) wc[wid] = __popc(bal);
    __syncthreads();
    if (threadIdx.x == 0) {
        int nmw = blockDim.x >> 5, acc = 0;
        for (int i = 0; i < nmw; i++) { ws[i] = acc; acc += wc[i]; }
    }
    __syncthreads();
    if (pred) {
        int idx = g_boff[blockIdx.x] + ws[wid] + __popc(bal & ((1u << lane) - 1u));
        g_ssrc[idx] = src[e];
        g_sdst[idx] = dst[e];
        #pragma unroll
        for (int k = 0; k < 6; k++) g_sea[idx * 6 + k] = ea[(size_t)e * 6 + k];
    }
}

// ============================ prep kernels ============================
__global__ void k_zero_agg() {
    int i = blockIdx.x * blockDim.x + threadIdx.x;
    if (i < NNODES * 3) g_agg[i] = 0.f;
}
__global__ void k_convW2(const float* __restrict__ W2) {
    int idx = blockIdx.x * blockDim.x + threadIdx.x;
    if (idx >= HID * HID) return;
    int n = idx / HID, k = idx - n * HID;
    float v = W2[k * HID + n];
    __nv_bfloat16 h = __float2bfloat16(v);
    g_w2thi[idx] = h;
    g_w2tlo[idx] = __float2bfloat16(v - __bfloat162float(h));
}
__global__ void k_convW3(const float* __restrict__ W3, const float* __restrict__ b3) {
    int idx = blockIdx.x * blockDim.x + threadIdx.x;
    if (idx >= MSGP * HID) return;
    int n = idx / HID, k = idx - n * HID;
    float v = (n < MSG) ? W3[k * MSG + n] : 0.f;
    __nv_bfloat16 h = __float2bfloat16(v);
    g_w3thi[idx] = h;
    g_w3tlo[idx] = __float2bfloat16(v - __bfloat162float(h));
    if (idx < MSGP) g_b3p[idx] = (idx < MSG) ? b3[idx] : 0.f;
}

// ============================ layer1: [Esel,6]@[6,768], leaky, split-bf16 out ============================
#define L1_EPB 8
__global__ void k_layer1(const float* __restrict__ W1, const float* __restrict__ b1, int esel) {
    int e0 = blockIdx.x * L1_EPB;
    __shared__ float ea[L1_EPB][6];
    int t = threadIdx.x;
    if (t < L1_EPB * 6) ea[t / 6][t % 6] = g_sea[e0 * 6 + t];
    __syncthreads();
    for (int n = t; n < HID; n += blockDim.x) {
        float w[6];
        #pragma unroll
        for (int k = 0; k < 6; k++) w[k] = W1[k * HID + n];
        float bb = b1[n];
        #pragma unroll
        for (int e = 0; e < L1_EPB; e++) {
            float acc = bb;
            #pragma unroll
            for (int k = 0; k < 6; k++) acc += ea[e][k] * w[k];
            float v = leaky(acc);
            __nv_bfloat16 h = __float2bfloat16(v);
            size_t o = (size_t)(e0 + e) * HID + n;
            g_h1hi[o] = h;
            g_h1lo[o] = __float2bfloat16(v - __bfloat162float(h));
        }
    }
}

// ============================ warp-MMA split-bf16 GEMM ============================
// C[128m,128n] = (Ahi+Alo)[m,k] @ (Bhi+Blo)[n,k]^T via 3 bf16 passes, fp32 acc regs.
// smem: 2 buffers x [Ahi|Alo|Bhi|Blo], each 128 rows x 32 bf16 (64B rows), chunk-XOR swizzle.
// 8 warps (2m x 4n), warp tile 64x32 -> 4x4 m16n8k16 tiles.
#define GBUF      32768
#define GEMM_SMEM (2 * GBUF + 128)

__global__ __launch_bounds__(256, 1)
void k_gemm_mma(const __nv_bfloat16* __restrict__ Ahi, const __nv_bfloat16* __restrict__ Alo,
                const __nv_bfloat16* __restrict__ Bhi, const __nv_bfloat16* __restrict__ Blo,
                const float* __restrict__ bias,
                float* __restrict__ Cf,
                __nv_bfloat16* __restrict__ Chi, __nv_bfloat16* __restrict__ Clo,
                int K, int ldc, int act_split)
{
    extern __shared__ char smem[];
    uint32_t sbase = (smem_to_u32(smem) + 127) & ~127u;
    int tid = threadIdx.x;
    int wid = tid >> 5, lane = tid & 31;
    int wm = wid >> 2, wn = wid & 3;
    int m0 = blockIdx.y * 128, n0 = blockIdx.x * 128;
    int S = K / 32;

    float acc[16][4];
    #pragma unroll
    for (int i = 0; i < 16; i++)
        #pragma unroll
        for (int j = 0; j < 4; j++) acc[i][j] = 0.f;

    // ---------- loader: 4 mats x 128 rows x 4 chunks(16B) = 2048 chunks, 8/thread ----------
    auto load_stage = [&](int s, int b) {
        uint32_t bo = sbase + (uint32_t)b * GBUF;
        #pragma unroll
        for (int t = 0; t < 8; t++) {
            const int mat = t >> 1;                  // 0:Ahi 1:Alo 2:Bhi 3:Blo
            int rem = tid + (t & 1) * 256;           // 0..511
            int row = rem >> 2;
            int c   = rem & 3;
            const __nv_bfloat16* g;
            int gr = (mat < 2 ? m0 : n0) + row;
            if      (mat == 0) g = Ahi + (size_t)gr * K;
            else if (mat == 1) g = Alo + (size_t)gr * K;
            else if (mat == 2) g = Bhi + (size_t)gr * K;
            else               g = Blo + (size_t)gr * K;
            g += s * 32 + c * 8;
            uint32_t dstr = bo + (uint32_t)mat * 8192 + (uint32_t)row * 64
                          + (uint32_t)((c ^ (row & 3)) << 4);
            cp16(dstr, g);
        }
    };

    // ---------- fragment address precompute ----------
    uint32_t aOff[4], bOff[4];
    uint32_t aR3[4], bR3[4];
    {
        int arow_base = wm * 64 + ((lane >> 3) & 1) * 8 + (lane & 7);
        #pragma unroll
        for (int mt = 0; mt < 4; mt++) {
            int r = arow_base + mt * 16;
            aOff[mt] = (uint32_t)r * 64;
            aR3[mt] = (uint32_t)(r & 3);
        }
        int brow_base = wn * 32 + (lane & 7);
        #pragma unroll
        for (int nt = 0; nt < 4; nt++) {
            int r = brow_base + nt * 8;
            bOff[nt] = 16384u + (uint32_t)r * 64;
            bR3[nt] = (uint32_t)(r & 3);
        }
    }
    uint32_t aKadd = (uint32_t)(lane >> 4);        // +0/+1 chunk for A matrices 2,3
    uint32_t bKadd = (uint32_t)((lane >> 3) & 1);  // +0/+1 chunk for B matrix 1

    auto compute = [&](int b) {
        uint32_t base = sbase + (uint32_t)b * GBUF;
        #pragma unroll
        for (int ks = 0; ks < 2; ks++) {
            uint32_t ahi[4][4], alo[4][4], bhi[4][2], blo[4][2];
            #pragma unroll
            for (int mt = 0; mt < 4; mt++) {
                uint32_t c = (uint32_t)(ks * 2) + aKadd;
                uint32_t addr = base + aOff[mt] + ((c ^ aR3[mt]) << 4);
                ldsm_x4(ahi[mt], addr);
                ldsm_x4(alo[mt], addr + 8192);
            }
            #pragma unroll
            for (int nt = 0; nt < 4; nt++) {
                uint32_t c = (uint32_t)(ks * 2) + bKadd;
                uint32_t addr = base + bOff[nt] + ((c ^ bR3[nt]) << 4);
                ldsm_x2(bhi[nt], addr);
                ldsm_x2(blo[nt], addr + 8192);
            }
            #pragma unroll
            for (int mt = 0; mt < 4; mt++)
                #pragma unroll
                for (int nt = 0; nt < 4; nt++) {
                    mma16816(acc[mt * 4 + nt], ahi[mt], bhi[nt]);
                    mma16816(acc[mt * 4 + nt], ahi[mt], blo[nt]);
                    mma16816(acc[mt * 4 + nt], alo[mt], bhi[nt]);
                }
        }
    };

    // ---------- pipelined main loop ----------
    load_stage(0, 0); CP_COMMIT;
    for (int s = 0; s < S; s++) {
        int b = s & 1;
        if (s + 1 < S) { load_stage(s + 1, b ^ 1); CP_COMMIT; CP_WAIT1; }
        else           { CP_WAIT0; }
        __syncthreads();
        compute(b);
        __syncthreads();
    }

    // ---------- epilogue ----------
    int r0 = m0 + wm * 64 + (lane >> 2);
    int c0 = n0 + wn * 32 + 2 * (lane & 3);
    #pragma unroll
    for (int mt = 0; mt < 4; mt++) {
        #pragma unroll
        for (int nt = 0; nt < 4; nt++) {
            int row = r0 + mt * 16;
            int col = c0 + nt * 8;
            const float* a = acc[mt * 4 + nt];
            float b0 = bias[col], b1 = bias[col + 1];
            float v00 = a[0] + b0, v01 = a[1] + b1;
            float v10 = a[2] + b0, v11 = a[3] + b1;
            if (act_split) {
                v00 = leaky(v00); v01 = leaky(v01); v10 = leaky(v10); v11 = leaky(v11);
                __nv_bfloat16 h00 = __float2bfloat16(v00), h01 = __float2bfloat16(v01);
                __nv_bfloat16 h10 = __float2bfloat16(v10), h11 = __float2bfloat16(v11);
                __nv_bfloat162 hh0; hh0.x = h00; hh0.y = h01;
                __nv_bfloat162 hh1; hh1.x = h10; hh1.y = h11;
                *(__nv_bfloat162*)(Chi + (size_t)row * ldc + col) = hh0;
                *(__nv_bfloat162*)(Chi + (size_t)(row + 8) * ldc + col) = hh1;
                __nv_bfloat162 ll0, ll1;
                ll0.x = __float2bfloat16(v00 - __bfloat162float(h00));
                ll0.y = __float2bfloat16(v01 - __bfloat162float(h01));
                ll1.x = __float2bfloat16(v10 - __bfloat162float(h10));
                ll1.y = __float2bfloat16(v11 - __bfloat162float(h11));
                *(__nv_bfloat162*)(Clo + (size_t)row * ldc + col) = ll0;
                *(__nv_bfloat162*)(Clo + (size_t)(row + 8) * ldc + col) = ll1;
            } else {
                float2 f0 = make_float2(v00, v01);
                float2 f1 = make_float2(v10, v11);
                *(float2*)(Cf + (size_t)row * ldc + col) = f0;
                *(float2*)(Cf + (size_t)(row + 8) * ldc + col) = f1;
            }
        }
    }
}

// ============================ poly products + einsum + antisym scatter ============================
__global__ void k_msg_scatter(int esel) {
    int gw = (blockIdx.x * blockDim.x + threadIdx.x) >> 5;
    int lane = threadIdx.x & 31;
    int wl = threadIdx.x >> 5;
    __shared__ float sprod[8][84];
    if (gw >= esel) return;

    if (lane == 0) {
        float ea[6];
        #pragma unroll
        for (int k = 0; k < 6; k++) ea[k] = g_sea[gw * 6 + k];
        int p = 0;
        #pragma unroll
        for (int a = 0; a < 6; a++) sprod[wl][p++] = ea[a];
        #pragma unroll
        for (int a = 0; a < 6; a++)
            for (int b = a; b < 6; b++) sprod[wl][p++] = ea[a] * ea[b];
        #pragma unroll
        for (int a = 0; a < 6; a++)
            for (int b = a; b < 6; b++)
                for (int c = b; c < 6; c++) sprod[wl][p++] = ea[a] * ea[b] * ea[c];
    }
    __syncwarp();

    float r0 = 0.f, r1 = 0.f, r2 = 0.f;
    const float* wrow = g_w + (size_t)gw * MSGP;
    for (int j = lane; j < MSG; j += 32) {
        int k = j / 83, p = j - k * 83;
        float t = wrow[j] * sprod[wl][p];
        if (k == 0) r0 += t; else if (k == 1) r1 += t; else r2 += t;
    }
    #pragma unroll
    for (int off = 16; off; off >>= 1) {
        r0 += __shfl_xor_sync(0xffffffffu, r0, off);
        r1 += __shfl_xor_sync(0xffffffffu, r1, off);
        r2 += __shfl_xor_sync(0xffffffffu, r2, off);
    }
    if (lane == 0) {
        int s = g_ssrc[gw], d = g_sdst[gw];
        atomicAdd(&g_agg[d * 3 + 0],  r0);
        atomicAdd(&g_agg[d * 3 + 1],  r1);
        atomicAdd(&g_agg[d * 3 + 2],  r2);
        atomicAdd(&g_agg[s * 3 + 0], -r0);
        atomicAdd(&g_agg[s * 3 + 1], -r1);
        atomicAdd(&g_agg[s * 3 + 2], -r2);
    }
}

// ============================ node update: LN(19)+MLP ============================
__global__ void k_update(const float* __restrict__ x,
                         const float* __restrict__ ln_g, const float* __restrict__ ln_b,
                         const float* __restrict__ uW1, const float* __restrict__ ub1,
                         const float* __restrict__ uW2, const float* __restrict__ ub2,
                         const float* __restrict__ uW3, const float* __restrict__ ub3,
                         float* __restrict__ out) {
    __shared__ float sW1[19 * 18], sW2[18 * 17], sW3[17 * 16];
    __shared__ float sb1[18], sb2[17], sb3[16], sg[19], sbt[19];
    int t = threadIdx.x;
    for (int i = t; i < 19 * 18; i += blockDim.x) sW1[i] = uW1[i];
    for (int i = t; i < 18 * 17; i += blockDim.x) sW2[i] = uW2[i];
    for (int i = t; i < 17 * 16; i += blockDim.x) sW3[i] = uW3[i];
    if (t < 18) sb1[t] = ub1[t];
    if (t < 17) sb2[t] = ub2[t];
    if (t < 16) sb3[t] = ub3[t];
    if (t < 19) { sg[t] = ln_g[t]; sbt[t] = ln_b[t]; }
    __syncthreads();

    int node = blockIdx.x * blockDim.x + t;
    if (node >= NNODES) return;

    float h[19];
    #pragma unroll
    for (int i = 0; i < 16; i++) h[i] = x[node * 16 + i];
    #pragma unroll
    for (int k = 0; k < 3; k++) h[16 + k] = g_agg[node * 3 + k];

    float mu = 0.f;
    #pragma unroll
    for (int i = 0; i < 19; i++) mu += h[i];
    mu *= (1.f / 19.f);
    float var = 0.f;
    #pragma unroll
    for (int i = 0; i < 19; i++) { float dlt = h[i] - mu; var += dlt * dlt; }
    var *= (1.f / 19.f);
    float rs = rsqrtf(var + LN_EPS);
    float hn[19];
    #pragma unroll
    for (int i = 0; i < 19; i++) hn[i] = (h[i] - mu) * rs * sg[i] + sbt[i];

    float t1[18];
    #pragma unroll
    for (int j = 0; j < 18; j++) {
        float acc = sb1[j];
        #pragma unroll
        for (int i = 0; i < 19; i++) acc += hn[i] * sW1[i * 18 + j];
        t1[j] = leaky(acc);
    }
    float t2[17];
    #pragma unroll
    for (int j = 0; j < 17; j++) {
        float acc = sb2[j];
        #pragma unroll
        for (int i = 0; i < 18; i++) acc += t1[i] * sW2[i * 17 + j];
        t2[j] = leaky(acc);
    }
    #pragma unroll
    for (int j = 0; j < 16; j++) {
        float acc = sb3[j];
        #pragma unroll
        for (int i = 0; i < 17; i++) acc += t2[i] * sW3[i * 16 + j];
        out[node * 16 + j] = acc;
    }
}

// ============================ launch ============================
extern "C" void kernel_launch(void* const* d_in, const int* in_sizes, int n_in,
                              void* d_out, int out_size) {
    const float* x    = (const float*)d_in[0];
    const float* ea   = (const float*)d_in[1];
    const float* mW1  = (const float*)d_in[2];
    const float* mb1  = (const float*)d_in[3];
    const float* mW2  = (const float*)d_in[4];
    const float* mb2  = (const float*)d_in[5];
    const float* mW3  = (const float*)d_in[6];
    const float* mb3  = (const float*)d_in[7];
    const float* ln_g = (const float*)d_in[8];
    const float* ln_b = (const float*)d_in[9];
    const float* uW1  = (const float*)d_in[10];
    const float* ub1  = (const float*)d_in[11];
    const float* uW2  = (const float*)d_in[12];
    const float* ub2  = (const float*)d_in[13];
    const float* uW3  = (const float*)d_in[14];
    const float* ub3  = (const float*)d_in[15];
    const int*   eidx = (const int*)d_in[16];

    int E = in_sizes[1] / 6;               // 131072
    const int* src = eidx;
    const int* dst = eidx + E;
    int esel = E / 2;                      // 65536
    int NB = (E + 1023) / 1024;

    __nv_bfloat16 *p_h1hi, *p_h1lo, *p_h2hi, *p_h2lo, *p_w2thi, *p_w2tlo, *p_w3thi, *p_w3tlo;
    float *p_w, *p_b3p;
    cudaGetSymbolAddress((void**)&p_h1hi,  g_h1hi);
    cudaGetSymbolAddress((void**)&p_h1lo,  g_h1lo);
    cudaGetSymbolAddress((void**)&p_h2hi,  g_h2hi);
    cudaGetSymbolAddress((void**)&p_h2lo,  g_h2lo);
    cudaGetSymbolAddress((void**)&p_w2thi, g_w2thi);
    cudaGetSymbolAddress((void**)&p_w2tlo, g_w2tlo);
    cudaGetSymbolAddress((void**)&p_w3thi, g_w3thi);
    cudaGetSymbolAddress((void**)&p_w3tlo, g_w3tlo);
    cudaGetSymbolAddress((void**)&p_w,     g_w);
    cudaGetSymbolAddress((void**)&p_b3p,   g_b3p);

    cudaFuncSetAttribute(k_gemm_mma, cudaFuncAttributeMaxDynamicSharedMemorySize, GEMM_SMEM);

    k_zero_agg<<<(NNODES * 3 + 255) / 256, 256>>>();
    k_count  <<<NB, 1024>>>(src, dst, E);
    k_scan   <<<1, 1024>>>(NB);
    k_scatter<<<NB, 1024>>>(src, dst, ea, E);
    k_convW2 <<<(HID * HID + 255) / 256, 256>>>(mW2);
    k_convW3 <<<(MSGP * HID + 255) / 256, 256>>>(mW3, mb3);

    k_layer1 <<<esel / L1_EPB, 256>>>(mW1, mb1, esel);

    // GEMM2: h2 = leaky(h1 @ W2 + b2), split-bf16 out
    dim3 g2(HID / 128, esel / 128);
    k_gemm_mma<<<g2, 256, GEMM_SMEM>>>(p_h1hi, p_h1lo, p_w2thi, p_w2tlo, mb2,
                                       nullptr, p_h2hi, p_h2lo, HID, HID, 1);
    // GEMM3: w = h2 @ W3p + b3p, fp32 out
    dim3 g3(MSGP / 128, esel / 128);
    k_gemm_mma<<<g3, 256, GEMM_SMEM>>>(p_h2hi, p_h2lo, p_w3thi, p_w3tlo, p_b3p,
                                       p_w, nullptr, nullptr, HID, MSGP, 0);

    k_msg_scatter<<<(esel * 32 + 255) / 256, 256>>>(esel);

    k_update<<<(NNODES + 127) / 128, 128>>>(x, ln_g, ln_b, uW1, ub1, uW2, ub2,
                                            uW3, ub3, (float*)d_out);
}

// round 6
// speedup vs baseline: 2.8205x; 1.2270x over previous
#include <cuda_runtime.h>
#include <cuda_fp16.h>
#include <cstdint>

#define NNODES   8192
#define EMAX     131072
#define ESEL     65536
#define HID      768
#define MSG      249
#define MSGP     256
#define LN_EPS   1e-5f

// ============================ PTX helpers (baseline, sm_80+) ============================
__device__ __forceinline__ uint32_t smem_to_u32(const void* p) {
    uint32_t a;
    asm("{ .reg .u64 t; cvta.to.shared.u64 t, %1; cvt.u32.u64 %0, t; }" : "=r"(a) : "l"(p));
    return a;
}
__device__ __forceinline__ void cp16(uint32_t s, const void* g) {
    asm volatile("cp.async.cg.shared.global [%0], [%1], 16;" :: "r"(s), "l"(g));
}
#define CP_COMMIT  asm volatile("cp.async.commit_group;" ::: "memory")
#define CP_WAIT1   asm volatile("cp.async.wait_group 1;" ::: "memory")

__device__ __forceinline__ void ldsm_x4(uint32_t* r, uint32_t addr) {
    asm volatile("ldmatrix.sync.aligned.m8n8.x4.shared.b16 {%0,%1,%2,%3}, [%4];"
        : "=r"(r[0]), "=r"(r[1]), "=r"(r[2]), "=r"(r[3]) : "r"(addr));
}
__device__ __forceinline__ void ldsm_x2(uint32_t* r, uint32_t addr) {
    asm volatile("ldmatrix.sync.aligned.m8n8.x2.shared.b16 {%0,%1}, [%2];"
        : "=r"(r[0]), "=r"(r[1]) : "r"(addr));
}
__device__ __forceinline__ void mma16816(float* d, const uint32_t* a, const uint32_t* b) {
    asm volatile("mma.sync.aligned.m16n8k16.row.col.f32.f16.f16.f32 "
        "{%0,%1,%2,%3}, {%4,%5,%6,%7}, {%8,%9}, {%0,%1,%2,%3};"
        : "+f"(d[0]), "+f"(d[1]), "+f"(d[2]), "+f"(d[3])
        : "r"(a[0]), "r"(a[1]), "r"(a[2]), "r"(a[3]), "r"(b[0]), "r"(b[1]));
}

// ============================ scratch ============================
__device__ __half g_h1hi[(size_t)ESEL * HID];
__device__ __half g_h1lo[(size_t)ESEL * HID];
__device__ __half g_h2hi[(size_t)ESEL * HID];
__device__ __half g_h2lo[(size_t)ESEL * HID];
__device__ __half g_w2t[HID * HID];        // W2^T fp16
__device__ __half g_w3t[MSGP * HID];       // W3^T padded fp16
__device__ float g_b3p[MSGP];
__device__ float g_w[(size_t)ESEL * MSGP];
__device__ float g_sea[ESEL * 6];
__device__ int   g_ssrc[ESEL];
__device__ int   g_sdst[ESEL];
__device__ float g_agg[NNODES * 3];
__device__ int   g_bcnt[1024];
__device__ int   g_boff[1024];

__device__ __forceinline__ float leaky(float v) { return v > 0.f ? v : 0.01f * v; }

// ============================ edge compaction (src < dst) ============================
__global__ void k_count(const int* __restrict__ src, const int* __restrict__ dst, int E) {
    int e = blockIdx.x * blockDim.x + threadIdx.x;
    int pred = (e < E) && (src[e] < dst[e]);
    unsigned bal = __ballot_sync(0xffffffffu, pred);
    __shared__ int wc[32];
    int wid = threadIdx.x >> 5, lane = threadIdx.x & 31;
    if (lane == 0) wc[wid] = __popc(bal);
    __syncthreads();
    if (threadIdx.x == 0) {
        int nmw = blockDim.x >> 5, s = 0;
        for (int i = 0; i < nmw; i++) s += wc[i];
        g_bcnt[blockIdx.x] = s;
    }
}
__global__ void k_scan(int nb) {
    __shared__ int s[1024];
    int t = threadIdx.x;
    if (t < nb) s[t] = g_bcnt[t];
    __syncthreads();
    if (t == 0) { int acc = 0; for (int i = 0; i < nb; i++) { int v = s[i]; s[i] = acc; acc += v; } }
    __syncthreads();
    if (t < nb) g_boff[t] = s[t];
}
__global__ void k_scatter(const int* __restrict__ src, const int* __restrict__ dst,
                          const float* __restrict__ ea, int E) {
    int e = blockIdx.x * blockDim.x + threadIdx.x;
    int pred = (e < E) && (src[e] < dst[e]);
    unsigned bal = __ballot_sync(0xffffffffu, pred);
    __shared__ int wc[32], ws[32];
    int wid = threadIdx.x >> 5, lane = threadIdx.x & 31;
    if (lane == 0) wc[wid] = __popc(bal);
    __syncthreads();
    if (threadIdx.x == 0) {
        int nmw = blockDim.x >> 5, acc = 0;
        for (int i = 0; i < nmw; i++) { ws[i] = acc; acc += wc[i]; }
    }
    __syncthreads();
    if (pred) {
        int idx = g_boff[blockIdx.x] + ws[wid] + __popc(bal & ((1u << lane) - 1u));
        g_ssrc[idx] = src[e];
        g_sdst[idx] = dst[e];
        #pragma unroll
        for (int k = 0; k < 6; k++) g_sea[idx * 6 + k] = ea[(size_t)e * 6 + k];
    }
}

// ============================ prep kernels ============================
__global__ void k_zero_agg() {
    int i = blockIdx.x * blockDim.x + threadIdx.x;
    if (i < NNODES * 3) g_agg[i] = 0.f;
}
__global__ void k_convW2(const float* __restrict__ W2) {
    int idx = blockIdx.x * blockDim.x + threadIdx.x;
    if (idx >= HID * HID) return;
    int n = idx / HID, k = idx - n * HID;
    g_w2t[idx] = __float2half_rn(W2[k * HID + n]);
}
__global__ void k_convW3(const float* __restrict__ W3, const float* __restrict__ b3) {
    int idx = blockIdx.x * blockDim.x + threadIdx.x;
    if (idx >= MSGP * HID) return;
    int n = idx / HID, k = idx - n * HID;
    g_w3t[idx] = __float2half_rn((n < MSG) ? W3[k * MSG + n] : 0.f);
    if (idx < MSGP) g_b3p[idx] = (idx < MSG) ? b3[idx] : 0.f;
}

// ============================ layer1: [Esel,6]@[6,768], leaky, split-fp16 out ============================
#define L1_EPB 8
__global__ void k_layer1(const float* __restrict__ W1, const float* __restrict__ b1, int esel) {
    int e0 = blockIdx.x * L1_EPB;
    __shared__ float ea[L1_EPB][6];
    int t = threadIdx.x;
    if (t < L1_EPB * 6) ea[t / 6][t % 6] = g_sea[e0 * 6 + t];
    __syncthreads();
    for (int n = t; n < HID; n += blockDim.x) {
        float w[6];
        #pragma unroll
        for (int k = 0; k < 6; k++) w[k] = W1[k * HID + n];
        float bb = b1[n];
        #pragma unroll
        for (int e = 0; e < L1_EPB; e++) {
            float acc = bb;
            #pragma unroll
            for (int k = 0; k < 6; k++) acc += ea[e][k] * w[k];
            float v = leaky(acc);
            __half h = __float2half_rn(v);
            size_t o = (size_t)(e0 + e) * HID + n;
            g_h1hi[o] = h;
            g_h1lo[o] = __float2half_rn(v - __half2float(h));
        }
    }
}

// ============================ warp-MMA 2-pass fp16 GEMM ============================
// C[128m,128n] = (Ahi+Alo)[m,k] @ B[n,k]^T, fp32 acc, 2 MMA passes.
// smem: 3-stage ring x [Ahi|Alo|B], each 128 rows x 32 fp16 (64B rows), chunk-XOR swizzle.
// 8 warps (2m x 4n), warp tile 64x32 -> 4x4 m16n8k16 tiles, pass-major MMA order.
#define GSTAGE    24576
#define GEMM_SMEM (3 * GSTAGE + 128)

__global__ __launch_bounds__(256, 1)
void k_gemm_mma(const __half* __restrict__ Ahi, const __half* __restrict__ Alo,
                const __half* __restrict__ B,
                const float* __restrict__ bias,
                float* __restrict__ Cf,
                __half* __restrict__ Chi, __half* __restrict__ Clo,
                int K, int ldc, int act_split)
{
    extern __shared__ char smem[];
    uint32_t sbase = (smem_to_u32(smem) + 127) & ~127u;
    int tid = threadIdx.x;
    int wid = tid >> 5, lane = tid & 31;
    int wm = wid >> 2, wn = wid & 3;
    int m0 = blockIdx.y * 128, n0 = blockIdx.x * 128;
    int S = K / 32;

    float acc[16][4];
    #pragma unroll
    for (int i = 0; i < 16; i++)
        #pragma unroll
        for (int j = 0; j < 4; j++) acc[i][j] = 0.f;

    // ---------- loader: 3 mats x 128 rows x 4 chunks(16B) = 1536 chunks, 6/thread ----------
    auto load_stage = [&](int s, int b) {
        uint32_t bo = sbase + (uint32_t)b * GSTAGE;
        #pragma unroll
        for (int t = 0; t < 6; t++) {
            int i   = tid + t * 256;            // 0..1535
            int mat = i >> 9;                   // 0:Ahi 1:Alo 2:B
            int rem = i & 511;
            int row = rem >> 2;
            int c   = rem & 3;
            const __half* g;
            int gr = (mat < 2 ? m0 : n0) + row;
            if      (mat == 0) g = Ahi + (size_t)gr * K;
            else if (mat == 1) g = Alo + (size_t)gr * K;
            else               g = B   + (size_t)gr * K;
            g += s * 32 + c * 8;
            uint32_t dstr = bo + (uint32_t)mat * 8192 + (uint32_t)row * 64
                          + (uint32_t)((c ^ (row & 3)) << 4);
            cp16(dstr, g);
        }
    };

    // ---------- fragment address precompute ----------
    uint32_t aOff[4], aR3[4], bOff[4], bR3[4];
    {
        int arow_base = wm * 64 + ((lane >> 3) & 1) * 8 + (lane & 7);
        #pragma unroll
        for (int mt = 0; mt < 4; mt++) {
            int r = arow_base + mt * 16;
            aOff[mt] = (uint32_t)r * 64;
            aR3[mt] = (uint32_t)(r & 3);
        }
        int brow_base = wn * 32 + (lane & 7);
        #pragma unroll
        for (int nt = 0; nt < 4; nt++) {
            int r = brow_base + nt * 8;
            bOff[nt] = 16384u + (uint32_t)r * 64;
            bR3[nt] = (uint32_t)(r & 3);
        }
    }
    uint32_t aKadd = (uint32_t)(lane >> 4);        // +1 chunk for lanes 16-31 (k+8 matrices)
    uint32_t bKadd = (uint32_t)((lane >> 3) & 1);  // +1 chunk for lanes 8-15

    auto compute = [&](int b) {
        uint32_t base = sbase + (uint32_t)b * GSTAGE;
        #pragma unroll
        for (int ks = 0; ks < 2; ks++) {
            uint32_t ahi[4][4], alo[4][4], bf[4][2];
            #pragma unroll
            for (int mt = 0; mt < 4; mt++) {
                uint32_t c = (uint32_t)(ks * 2) + aKadd;
                uint32_t addr = base + aOff[mt] + ((c ^ aR3[mt]) << 4);
                ldsm_x4(ahi[mt], addr);
                ldsm_x4(alo[mt], addr + 8192);
            }
            #pragma unroll
            for (int nt = 0; nt < 4; nt++) {
                uint32_t c = (uint32_t)(ks * 2) + bKadd;
                ldsm_x2(bf[nt], base + bOff[nt] + ((c ^ bR3[nt]) << 4));
            }
            // pass-major: 16 independent accumulators between reuses
            #pragma unroll
            for (int mt = 0; mt < 4; mt++)
                #pragma unroll
                for (int nt = 0; nt < 4; nt++)
                    mma16816(acc[mt * 4 + nt], ahi[mt], bf[nt]);
            #pragma unroll
            for (int mt = 0; mt < 4; mt++)
                #pragma unroll
                for (int nt = 0; nt < 4; nt++)
                    mma16816(acc[mt * 4 + nt], alo[mt], bf[nt]);
        }
    };

    // ---------- 3-stage pipelined main loop (one syncthreads per stage) ----------
    load_stage(0, 0); CP_COMMIT;
    load_stage(1, 1); CP_COMMIT;
    for (int s = 0; s < S; s++) {
        CP_WAIT1;                 // stage s resident
        __syncthreads();
        if (s + 2 < S) load_stage(s + 2, (s + 2) % 3);
        CP_COMMIT;                // empty group ok at tail
        compute(s % 3);
    }

    // ---------- epilogue ----------
    int r0 = m0 + wm * 64 + (lane >> 2);
    int c0 = n0 + wn * 32 + 2 * (lane & 3);
    #pragma unroll
    for (int mt = 0; mt < 4; mt++) {
        #pragma unroll
        for (int nt = 0; nt < 4; nt++) {
            int row = r0 + mt * 16;
            int col = c0 + nt * 8;
            const float* a = acc[mt * 4 + nt];
            float b0 = bias[col], b1 = bias[col + 1];
            float v00 = a[0] + b0, v01 = a[1] + b1;
            float v10 = a[2] + b0, v11 = a[3] + b1;
            if (act_split) {
                v00 = leaky(v00); v01 = leaky(v01); v10 = leaky(v10); v11 = leaky(v11);
                __half h00 = __float2half_rn(v00), h01 = __float2half_rn(v01);
                __half h10 = __float2half_rn(v10), h11 = __float2half_rn(v11);
                __half2 hh0; hh0.x = h00; hh0.y = h01;
                __half2 hh1; hh1.x = h10; hh1.y = h11;
                *(__half2*)(Chi + (size_t)row * ldc + col) = hh0;
                *(__half2*)(Chi + (size_t)(row + 8) * ldc + col) = hh1;
                __half2 ll0, ll1;
                ll0.x = __float2half_rn(v00 - __half2float(h00));
                ll0.y = __float2half_rn(v01 - __half2float(h01));
                ll1.x = __float2half_rn(v10 - __half2float(h10));
                ll1.y = __float2half_rn(v11 - __half2float(h11));
                *(__half2*)(Clo + (size_t)row * ldc + col) = ll0;
                *(__half2*)(Clo + (size_t)(row + 8) * ldc + col) = ll1;
            } else {
                *(float2*)(Cf + (size_t)row * ldc + col) = make_float2(v00, v01);
                *(float2*)(Cf + (size_t)(row + 8) * ldc + col) = make_float2(v10, v11);
            }
        }
    }
}

// ============================ poly products + einsum + antisym scatter ============================
__global__ void k_msg_scatter(int esel) {
    int gw = (blockIdx.x * blockDim.x + threadIdx.x) >> 5;
    int lane = threadIdx.x & 31;
    int wl = threadIdx.x >> 5;
    __shared__ float sprod[8][84];
    if (gw >= esel) return;

    if (lane == 0) {
        float ea[6];
        #pragma unroll
        for (int k = 0; k < 6; k++) ea[k] = g_sea[gw * 6 + k];
        int p = 0;
        #pragma unroll
        for (int a = 0; a < 6; a++) sprod[wl][p++] = ea[a];
        #pragma unroll
        for (int a = 0; a < 6; a++)
            for (int b = a; b < 6; b++) sprod[wl][p++] = ea[a] * ea[b];
        #pragma unroll
        for (int a = 0; a < 6; a++)
            for (int b = a; b < 6; b++)
                for (int c = b; c < 6; c++) sprod[wl][p++] = ea[a] * ea[b] * ea[c];
    }
    __syncwarp();

    float r0 = 0.f, r1 = 0.f, r2 = 0.f;
    const float* wrow = g_w + (size_t)gw * MSGP;
    for (int j = lane; j < MSG; j += 32) {
        int k = j / 83, p = j - k * 83;
        float t = wrow[j] * sprod[wl][p];
        if (k == 0) r0 += t; else if (k == 1) r1 += t; else r2 += t;
    }
    #pragma unroll
    for (int off = 16; off; off >>= 1) {
        r0 += __shfl_xor_sync(0xffffffffu, r0, off);
        r1 += __shfl_xor_sync(0xffffffffu, r1, off);
        r2 += __shfl_xor_sync(0xffffffffu, r2, off);
    }
    if (lane == 0) {
        int s = g_ssrc[gw], d = g_sdst[gw];
        atomicAdd(&g_agg[d * 3 + 0],  r0);
        atomicAdd(&g_agg[d * 3 + 1],  r1);
        atomicAdd(&g_agg[d * 3 + 2],  r2);
        atomicAdd(&g_agg[s * 3 + 0], -r0);
        atomicAdd(&g_agg[s * 3 + 1], -r1);
        atomicAdd(&g_agg[s * 3 + 2], -r2);
    }
}

// ============================ node update: LN(19)+MLP ============================
__global__ void k_update(const float* __restrict__ x,
                         const float* __restrict__ ln_g, const float* __restrict__ ln_b,
                         const float* __restrict__ uW1, const float* __restrict__ ub1,
                         const float* __restrict__ uW2, const float* __restrict__ ub2,
                         const float* __restrict__ uW3, const float* __restrict__ ub3,
                         float* __restrict__ out) {
    __shared__ float sW1[19 * 18], sW2[18 * 17], sW3[17 * 16];
    __shared__ float sb1[18], sb2[17], sb3[16], sg[19], sbt[19];
    int t = threadIdx.x;
    for (int i = t; i < 19 * 18; i += blockDim.x) sW1[i] = uW1[i];
    for (int i = t; i < 18 * 17; i += blockDim.x) sW2[i] = uW2[i];
    for (int i = t; i < 17 * 16; i += blockDim.x) sW3[i] = uW3[i];
    if (t < 18) sb1[t] = ub1[t];
    if (t < 17) sb2[t] = ub2[t];
    if (t < 16) sb3[t] = ub3[t];
    if (t < 19) { sg[t] = ln_g[t]; sbt[t] = ln_b[t]; }
    __syncthreads();

    int node = blockIdx.x * blockDim.x + t;
    if (node >= NNODES) return;

    float h[19];
    #pragma unroll
    for (int i = 0; i < 16; i++) h[i] = x[node * 16 + i];
    #pragma unroll
    for (int k = 0; k < 3; k++) h[16 + k] = g_agg[node * 3 + k];

    float mu = 0.f;
    #pragma unroll
    for (int i = 0; i < 19; i++) mu += h[i];
    mu *= (1.f / 19.f);
    float var = 0.f;
    #pragma unroll
    for (int i = 0; i < 19; i++) { float dlt = h[i] - mu; var += dlt * dlt; }
    var *= (1.f / 19.f);
    float rs = rsqrtf(var + LN_EPS);
    float hn[19];
    #pragma unroll
    for (int i = 0; i < 19; i++) hn[i] = (h[i] - mu) * rs * sg[i] + sbt[i];

    float t1[18];
    #pragma unroll
    for (int j = 0; j < 18; j++) {
        float acc = sb1[j];
        #pragma unroll
        for (int i = 0; i < 19; i++) acc += hn[i] * sW1[i * 18 + j];
        t1[j] = leaky(acc);
    }
    float t2[17];
    #pragma unroll
    for (int j = 0; j < 17; j++) {
        float acc = sb2[j];
        #pragma unroll
        for (int i = 0; i < 18; i++) acc += t1[i] * sW2[i * 17 + j];
        t2[j] = leaky(acc);
    }
    #pragma unroll
    for (int j = 0; j < 16; j++) {
        float acc = sb3[j];
        #pragma unroll
        for (int i = 0; i < 17; i++) acc += t2[i] * sW3[i * 16 + j];
        out[node * 16 + j] = acc;
    }
}

// ============================ launch ============================
extern "C" void kernel_launch(void* const* d_in, const int* in_sizes, int n_in,
                              void* d_out, int out_size) {
    const float* x    = (const float*)d_in[0];
    const float* ea   = (const float*)d_in[1];
    const float* mW1  = (const float*)d_in[2];
    const float* mb1  = (const float*)d_in[3];
    const float* mW2  = (const float*)d_in[4];
    const float* mb2  = (const float*)d_in[5];
    const float* mW3  = (const float*)d_in[6];
    const float* mb3  = (const float*)d_in[7];
    const float* ln_g = (const float*)d_in[8];
    const float* ln_b = (const float*)d_in[9];
    const float* uW1  = (const float*)d_in[10];
    const float* ub1  = (const float*)d_in[11];
    const float* uW2  = (const float*)d_in[12];
    const float* ub2  = (const float*)d_in[13];
    const float* uW3  = (const float*)d_in[14];
    const float* ub3  = (const float*)d_in[15];
    const int*   eidx = (const int*)d_in[16];

    int E = in_sizes[1] / 6;               // 131072
    const int* src = eidx;
    const int* dst = eidx + E;
    int esel = E / 2;                      // 65536
    int NB = (E + 1023) / 1024;

    __half *p_h1hi, *p_h1lo, *p_h2hi, *p_h2lo, *p_w2t, *p_w3t;
    float *p_w, *p_b3p;
    cudaGetSymbolAddress((void**)&p_h1hi, g_h1hi);
    cudaGetSymbolAddress((void**)&p_h1lo, g_h1lo);
    cudaGetSymbolAddress((void**)&p_h2hi, g_h2hi);
    cudaGetSymbolAddress((void**)&p_h2lo, g_h2lo);
    cudaGetSymbolAddress((void**)&p_w2t,  g_w2t);
    cudaGetSymbolAddress((void**)&p_w3t,  g_w3t);
    cudaGetSymbolAddress((void**)&p_w,    g_w);
    cudaGetSymbolAddress((void**)&p_b3p,  g_b3p);

    cudaFuncSetAttribute(k_gemm_mma, cudaFuncAttributeMaxDynamicSharedMemorySize, GEMM_SMEM);

    k_zero_agg<<<(NNODES * 3 + 255) / 256, 256>>>();
    k_count  <<<NB, 1024>>>(src, dst, E);
    k_scan   <<<1, 1024>>>(NB);
    k_scatter<<<NB, 1024>>>(src, dst, ea, E);
    k_convW2 <<<(HID * HID + 255) / 256, 256>>>(mW2);
    k_convW3 <<<(MSGP * HID + 255) / 256, 256>>>(mW3, mb3);

    k_layer1 <<<esel / L1_EPB, 256>>>(mW1, mb1, esel);

    // GEMM2: h2 = leaky(h1 @ W2 + b2), split-fp16 out
    dim3 g2(HID / 128, esel / 128);
    k_gemm_mma<<<g2, 256, GEMM_SMEM>>>(p_h1hi, p_h1lo, p_w2t, mb2,
                                       nullptr, p_h2hi, p_h2lo, HID, HID, 1);
    // GEMM3: w = h2 @ W3p + b3p, fp32 out
    dim3 g3(MSGP / 128, esel / 128);
    k_gemm_mma<<<g3, 256, GEMM_SMEM>>>(p_h2hi, p_h2lo, p_w3t, p_b3p,
                                       p_w, nullptr, nullptr, HID, MSGP, 0);

    k_msg_scatter<<<(esel * 32 + 255) / 256, 256>>>(esel);

    k_update<<<(NNODES + 127) / 128, 128>>>(x, ln_g, ln_b, uW1, ub1, uW2, ub2,
                                            uW3, ub3, (float*)d_out);
}

// round 7
// speedup vs baseline: 4.1035x; 1.4549x over previous
#include <cuda_runtime.h>
#include <cuda_fp16.h>
#include <cstdint>

#define NNODES   8192
#define EMAX     131072
#define ESEL     65536
#define HID      768
#define MSG      249
#define MSGP     256
#define LN_EPS   1e-5f

// ============================ PTX helpers (baseline, sm_80+) ============================
__device__ __forceinline__ uint32_t smem_to_u32(const void* p) {
    uint32_t a;
    asm("{ .reg .u64 t; cvta.to.shared.u64 t, %1; cvt.u32.u64 %0, t; }" : "=r"(a) : "l"(p));
    return a;
}
__device__ __forceinline__ void cp16(uint32_t s, const void* g) {
    asm volatile("cp.async.cg.shared.global [%0], [%1], 16;" :: "r"(s), "l"(g));
}
#define CP_COMMIT  asm volatile("cp.async.commit_group;" ::: "memory")
#define CP_WAIT2   asm volatile("cp.async.wait_group 2;" ::: "memory")

__device__ __forceinline__ void ldsm_x4(uint32_t* r, uint32_t addr) {
    asm volatile("ldmatrix.sync.aligned.m8n8.x4.shared.b16 {%0,%1,%2,%3}, [%4];"
        : "=r"(r[0]), "=r"(r[1]), "=r"(r[2]), "=r"(r[3]) : "r"(addr));
}
__device__ __forceinline__ void ldsm_x2(uint32_t* r, uint32_t addr) {
    asm volatile("ldmatrix.sync.aligned.m8n8.x2.shared.b16 {%0,%1}, [%2];"
        : "=r"(r[0]), "=r"(r[1]) : "r"(addr));
}
__device__ __forceinline__ void mma16816(float* d, const uint32_t* a, const uint32_t* b) {
    asm volatile("mma.sync.aligned.m16n8k16.row.col.f32.f16.f16.f32 "
        "{%0,%1,%2,%3}, {%4,%5,%6,%7}, {%8,%9}, {%0,%1,%2,%3};"
        : "+f"(d[0]), "+f"(d[1]), "+f"(d[2]), "+f"(d[3])
        : "r"(a[0]), "r"(a[1]), "r"(a[2]), "r"(a[3]), "r"(b[0]), "r"(b[1]));
}

// ============================ scratch ============================
__device__ __half g_h1[(size_t)ESEL * HID];    // layer1 out, fp16
__device__ __half g_h2[(size_t)ESEL * HID];    // layer2 out, fp16
__device__ __half g_w2t[HID * HID];            // W2^T fp16
__device__ __half g_w3t[MSGP * HID];           // W3^T padded fp16
__device__ float g_b3p[MSGP];
__device__ float g_w[(size_t)ESEL * MSGP];
__device__ float g_sea[ESEL * 6];
__device__ int   g_ssrc[ESEL];
__device__ int   g_sdst[ESEL];
__device__ float g_agg[NNODES * 3];
__device__ int   g_bcnt[1024];
__device__ int   g_boff[1024];

__device__ __forceinline__ float leaky(float v) { return v > 0.f ? v : 0.01f * v; }

// ============================ edge compaction (src < dst) ============================
__global__ void k_count(const int* __restrict__ src, const int* __restrict__ dst, int E) {
    int e = blockIdx.x * blockDim.x + threadIdx.x;
    int pred = (e < E) && (src[e] < dst[e]);
    unsigned bal = __ballot_sync(0xffffffffu, pred);
    __shared__ int wc[32];
    int wid = threadIdx.x >> 5, lane = threadIdx.x & 31;
    if (lane == 0) wc[wid] = __popc(bal);
    __syncthreads();
    if (threadIdx.x == 0) {
        int nmw = blockDim.x >> 5, s = 0;
        for (int i = 0; i < nmw; i++) s += wc[i];
        g_bcnt[blockIdx.x] = s;
    }
}
__global__ void k_scan(int nb) {
    __shared__ int s[1024];
    int t = threadIdx.x;
    if (t < nb) s[t] = g_bcnt[t];
    __syncthreads();
    if (t == 0) { int acc = 0; for (int i = 0; i < nb; i++) { int v = s[i]; s[i] = acc; acc += v; } }
    __syncthreads();
    if (t < nb) g_boff[t] = s[t];
}
__global__ void k_scatter(const int* __restrict__ src, const int* __restrict__ dst,
                          const float* __restrict__ ea, int E) {
    int e = blockIdx.x * blockDim.x + threadIdx.x;
    int pred = (e < E) && (src[e] < dst[e]);
    unsigned bal = __ballot_sync(0xffffffffu, pred);
    __shared__ int wc[32], ws[32];
    int wid = threadIdx.x >> 5, lane = threadIdx.x & 31;
    if (lane == 0) wc[wid] = __popc(bal);
    __syncthreads();
    if (threadIdx.x == 0) {
        int nmw = blockDim.x >> 5, acc = 0;
        for (int i = 0; i < nmw; i++) { ws[i] = acc; acc += wc[i]; }
    }
    __syncthreads();
    if (pred) {
        int idx = g_boff[blockIdx.x] + ws[wid] + __popc(bal & ((1u << lane) - 1u));
        g_ssrc[idx] = src[e];
        g_sdst[idx] = dst[e];
        #pragma unroll
        for (int k = 0; k < 6; k++) g_sea[idx * 6 + k] = ea[(size_t)e * 6 + k];
    }
}

// ============================ prep kernels ============================
__global__ void k_zero_agg() {
    int i = blockIdx.x * blockDim.x + threadIdx.x;
    if (i < NNODES * 3) g_agg[i] = 0.f;
}
__global__ void k_convW2(const float* __restrict__ W2) {
    int idx = blockIdx.x * blockDim.x + threadIdx.x;
    if (idx >= HID * HID) return;
    int n = idx / HID, k = idx - n * HID;
    g_w2t[idx] = __float2half_rn(W2[k * HID + n]);
}
__global__ void k_convW3(const float* __restrict__ W3, const float* __restrict__ b3) {
    int idx = blockIdx.x * blockDim.x + threadIdx.x;
    if (idx >= MSGP * HID) return;
    int n = idx / HID, k = idx - n * HID;
    g_w3t[idx] = __float2half_rn((n < MSG) ? W3[k * MSG + n] : 0.f);
    if (idx < MSGP) g_b3p[idx] = (idx < MSG) ? b3[idx] : 0.f;
}

// ============================ layer1: [Esel,6]@[6,768], leaky, fp16 out ============================
#define L1_EPB 8
__global__ void k_layer1(const float* __restrict__ W1, const float* __restrict__ b1, int esel) {
    int e0 = blockIdx.x * L1_EPB;
    __shared__ float ea[L1_EPB][6];
    int t = threadIdx.x;
    if (t < L1_EPB * 6) ea[t / 6][t % 6] = g_sea[e0 * 6 + t];
    __syncthreads();
    for (int n = t; n < HID; n += blockDim.x) {
        float w[6];
        #pragma unroll
        for (int k = 0; k < 6; k++) w[k] = W1[k * HID + n];
        float bb = b1[n];
        #pragma unroll
        for (int e = 0; e < L1_EPB; e++) {
            float acc = bb;
            #pragma unroll
            for (int k = 0; k < 6; k++) acc += ea[e][k] * w[k];
            g_h1[(size_t)(e0 + e) * HID + n] = __float2half_rn(leaky(acc));
        }
    }
}

// ============================ warp-MMA single-fp16 GEMM ============================
// C[128m,128n] = A[m,k] @ B[n,k]^T, fp32 acc, single pass.
// smem: 4-stage ring x [A|B], each 128 rows x 32 fp16 (64B rows), chunk-XOR swizzle.
// 8 warps (2m x 4n), warp tile 64x32 -> 4x4 m16n8k16 tiles.
#define GSTAGE    16384
#define GEMM_SMEM (4 * GSTAGE + 128)

__global__ __launch_bounds__(256, 1)
void k_gemm_mma(const __half* __restrict__ A, const __half* __restrict__ B,
                const float* __restrict__ bias,
                float* __restrict__ Cf, __half* __restrict__ Ch,
                int K, int ldc, int act)
{
    extern __shared__ char smem[];
    uint32_t sbase = (smem_to_u32(smem) + 127) & ~127u;
    int tid = threadIdx.x;
    int wid = tid >> 5, lane = tid & 31;
    int wm = wid >> 2, wn = wid & 3;
    int m0 = blockIdx.y * 128, n0 = blockIdx.x * 128;
    int S = K / 32;

    float acc[16][4];
    #pragma unroll
    for (int i = 0; i < 16; i++)
        #pragma unroll
        for (int j = 0; j < 4; j++) acc[i][j] = 0.f;

    // ---------- loader: 2 mats x 128 rows x 4 chunks(16B) = 1024 chunks, 4/thread ----------
    auto load_stage = [&](int s, int b) {
        uint32_t bo = sbase + (uint32_t)b * GSTAGE;
        #pragma unroll
        for (int t = 0; t < 4; t++) {
            int i   = tid + t * 256;            // 0..1023
            int mat = i >> 9;                   // 0:A 1:B
            int rem = i & 511;
            int row = rem >> 2;
            int c   = rem & 3;
            const __half* g = (mat == 0 ? A + (size_t)(m0 + row) * K
                                        : B + (size_t)(n0 + row) * K);
            g += s * 32 + c * 8;
            uint32_t dstr = bo + (uint32_t)mat * 8192 + (uint32_t)row * 64
                          + (uint32_t)((c ^ (row & 3)) << 4);
            cp16(dstr, g);
        }
    };

    // ---------- fragment address precompute ----------
    uint32_t aOff[4], aR3[4], bOff[4], bR3[4];
    {
        int arow_base = wm * 64 + ((lane >> 3) & 1) * 8 + (lane & 7);
        #pragma unroll
        for (int mt = 0; mt < 4; mt++) {
            int r = arow_base + mt * 16;
            aOff[mt] = (uint32_t)r * 64;
            aR3[mt] = (uint32_t)(r & 3);
        }
        int brow_base = wn * 32 + (lane & 7);
        #pragma unroll
        for (int nt = 0; nt < 4; nt++) {
            int r = brow_base + nt * 8;
            bOff[nt] = 8192u + (uint32_t)r * 64;
            bR3[nt] = (uint32_t)(r & 3);
        }
    }
    uint32_t aKadd = (uint32_t)(lane >> 4);        // +1 chunk for lanes 16-31
    uint32_t bKadd = (uint32_t)((lane >> 3) & 1);  // +1 chunk for lanes 8-15

    auto compute = [&](int b) {
        uint32_t base = sbase + (uint32_t)b * GSTAGE;
        #pragma unroll
        for (int ks = 0; ks < 2; ks++) {
            uint32_t af[4][4], bf[4][2];
            #pragma unroll
            for (int mt = 0; mt < 4; mt++) {
                uint32_t c = (uint32_t)(ks * 2) + aKadd;
                ldsm_x4(af[mt], base + aOff[mt] + ((c ^ aR3[mt]) << 4));
            }
            #pragma unroll
            for (int nt = 0; nt < 4; nt++) {
                uint32_t c = (uint32_t)(ks * 2) + bKadd;
                ldsm_x2(bf[nt], base + bOff[nt] + ((c ^ bR3[nt]) << 4));
            }
            #pragma unroll
            for (int mt = 0; mt < 4; mt++)
                #pragma unroll
                for (int nt = 0; nt < 4; nt++)
                    mma16816(acc[mt * 4 + nt], af[mt], bf[nt]);
        }
    };

    // ---------- 4-stage pipelined main loop (one syncthreads per stage) ----------
    load_stage(0, 0); CP_COMMIT;
    load_stage(1, 1); CP_COMMIT;
    load_stage(2, 2); CP_COMMIT;
    for (int s = 0; s < S; s++) {
        CP_WAIT2;                 // stage s resident (<=2 younger groups in flight)
        __syncthreads();
        if (s + 3 < S) load_stage(s + 3, (s + 3) & 3);
        CP_COMMIT;                // empty group ok at tail
        compute(s & 3);
    }

    // ---------- epilogue ----------
    int r0 = m0 + wm * 64 + (lane >> 2);
    int c0 = n0 + wn * 32 + 2 * (lane & 3);
    #pragma unroll
    for (int mt = 0; mt < 4; mt++) {
        #pragma unroll
        for (int nt = 0; nt < 4; nt++) {
            int row = r0 + mt * 16;
            int col = c0 + nt * 8;
            const float* a = acc[mt * 4 + nt];
            float b0 = bias[col], b1 = bias[col + 1];
            float v00 = a[0] + b0, v01 = a[1] + b1;
            float v10 = a[2] + b0, v11 = a[3] + b1;
            if (act) {
                v00 = leaky(v00); v01 = leaky(v01); v10 = leaky(v10); v11 = leaky(v11);
                __half2 hh0; hh0.x = __float2half_rn(v00); hh0.y = __float2half_rn(v01);
                __half2 hh1; hh1.x = __float2half_rn(v10); hh1.y = __float2half_rn(v11);
                *(__half2*)(Ch + (size_t)row * ldc + col) = hh0;
                *(__half2*)(Ch + (size_t)(row + 8) * ldc + col) = hh1;
            } else {
                *(float2*)(Cf + (size_t)row * ldc + col) = make_float2(v00, v01);
                *(float2*)(Cf + (size_t)(row + 8) * ldc + col) = make_float2(v10, v11);
            }
        }
    }
}

// ============================ poly products + einsum + antisym scatter ============================
__global__ void k_msg_scatter(int esel) {
    int gw = (blockIdx.x * blockDim.x + threadIdx.x) >> 5;
    int lane = threadIdx.x & 31;
    int wl = threadIdx.x >> 5;
    __shared__ float sprod[8][84];
    if (gw >= esel) return;

    if (lane == 0) {
        float ea[6];
        #pragma unroll
        for (int k = 0; k < 6; k++) ea[k] = g_sea[gw * 6 + k];
        int p = 0;
        #pragma unroll
        for (int a = 0; a < 6; a++) sprod[wl][p++] = ea[a];
        #pragma unroll
        for (int a = 0; a < 6; a++)
            for (int b = a; b < 6; b++) sprod[wl][p++] = ea[a] * ea[b];
        #pragma unroll
        for (int a = 0; a < 6; a++)
            for (int b = a; b < 6; b++)
                for (int c = b; c < 6; c++) sprod[wl][p++] = ea[a] * ea[b] * ea[c];
    }
    __syncwarp();

    float r0 = 0.f, r1 = 0.f, r2 = 0.f;
    const float* wrow = g_w + (size_t)gw * MSGP;
    for (int j = lane; j < MSG; j += 32) {
        int k = j / 83, p = j - k * 83;
        float t = wrow[j] * sprod[wl][p];
        if (k == 0) r0 += t; else if (k == 1) r1 += t; else r2 += t;
    }
    #pragma unroll
    for (int off = 16; off; off >>= 1) {
        r0 += __shfl_xor_sync(0xffffffffu, r0, off);
        r1 += __shfl_xor_sync(0xffffffffu, r1, off);
        r2 += __shfl_xor_sync(0xffffffffu, r2, off);
    }
    if (lane == 0) {
        int s = g_ssrc[gw], d = g_sdst[gw];
        atomicAdd(&g_agg[d * 3 + 0],  r0);
        atomicAdd(&g_agg[d * 3 + 1],  r1);
        atomicAdd(&g_agg[d * 3 + 2],  r2);
        atomicAdd(&g_agg[s * 3 + 0], -r0);
        atomicAdd(&g_agg[s * 3 + 1], -r1);
        atomicAdd(&g_agg[s * 3 + 2], -r2);
    }
}

// ============================ node update: LN(19)+MLP ============================
__global__ void k_update(const float* __restrict__ x,
                         const float* __restrict__ ln_g, const float* __restrict__ ln_b,
                         const float* __restrict__ uW1, const float* __restrict__ ub1,
                         const float* __restrict__ uW2, const float* __restrict__ ub2,
                         const float* __restrict__ uW3, const float* __restrict__ ub3,
                         float* __restrict__ out) {
    __shared__ float sW1[19 * 18], sW2[18 * 17], sW3[17 * 16];
    __shared__ float sb1[18], sb2[17], sb3[16], sg[19], sbt[19];
    int t = threadIdx.x;
    for (int i = t; i < 19 * 18; i += blockDim.x) sW1[i] = uW1[i];
    for (int i = t; i < 18 * 17; i += blockDim.x) sW2[i] = uW2[i];
    for (int i = t; i < 17 * 16; i += blockDim.x) sW3[i] = uW3[i];
    if (t < 18) sb1[t] = ub1[t];
    if (t < 17) sb2[t] = ub2[t];
    if (t < 16) sb3[t] = ub3[t];
    if (t < 19) { sg[t] = ln_g[t]; sbt[t] = ln_b[t]; }
    __syncthreads();

    int node = blockIdx.x * blockDim.x + t;
    if (node >= NNODES) return;

    float h[19];
    #pragma unroll
    for (int i = 0; i < 16; i++) h[i] = x[node * 16 + i];
    #pragma unroll
    for (int k = 0; k < 3; k++) h[16 + k] = g_agg[node * 3 + k];

    float mu = 0.f;
    #pragma unroll
    for (int i = 0; i < 19; i++) mu += h[i];
    mu *= (1.f / 19.f);
    float var = 0.f;
    #pragma unroll
    for (int i = 0; i < 19; i++) { float dlt = h[i] - mu; var += dlt * dlt; }
    var *= (1.f / 19.f);
    float rs = rsqrtf(var + LN_EPS);
    float hn[19];
    #pragma unroll
    for (int i = 0; i < 19; i++) hn[i] = (h[i] - mu) * rs * sg[i] + sbt[i];

    float t1[18];
    #pragma unroll
    for (int j = 0; j < 18; j++) {
        float acc = sb1[j];
        #pragma unroll
        for (int i = 0; i < 19; i++) acc += hn[i] * sW1[i * 18 + j];
        t1[j] = leaky(acc);
    }
    float t2[17];
    #pragma unroll
    for (int j = 0; j < 17; j++) {
        float acc = sb2[j];
        #pragma unroll
        for (int i = 0; i < 18; i++) acc += t1[i] * sW2[i * 17 + j];
        t2[j] = leaky(acc);
    }
    #pragma unroll
    for (int j = 0; j < 16; j++) {
        float acc = sb3[j];
        #pragma unroll
        for (int i = 0; i < 17; i++) acc += t2[i] * sW3[i * 16 + j];
        out[node * 16 + j] = acc;
    }
}

// ============================ launch ============================
extern "C" void kernel_launch(void* const* d_in, const int* in_sizes, int n_in,
                              void* d_out, int out_size) {
    const float* x    = (const float*)d_in[0];
    const float* ea   = (const float*)d_in[1];
    const float* mW1  = (const float*)d_in[2];
    const float* mb1  = (const float*)d_in[3];
    const float* mW2  = (const float*)d_in[4];
    const float* mb2  = (const float*)d_in[5];
    const float* mW3  = (const float*)d_in[6];
    const float* mb3  = (const float*)d_in[7];
    const float* ln_g = (const float*)d_in[8];
    const float* ln_b = (const float*)d_in[9];
    const float* uW1  = (const float*)d_in[10];
    const float* ub1  = (const float*)d_in[11];
    const float* uW2  = (const float*)d_in[12];
    const float* ub2  = (const float*)d_in[13];
    const float* uW3  = (const float*)d_in[14];
    const float* ub3  = (const float*)d_in[15];
    const int*   eidx = (const int*)d_in[16];

    int E = in_sizes[1] / 6;               // 131072
    const int* src = eidx;
    const int* dst = eidx + E;
    int esel = E / 2;                      // 65536
    int NB = (E + 1023) / 1024;

    __half *p_h1, *p_h2, *p_w2t, *p_w3t;
    float *p_w, *p_b3p;
    cudaGetSymbolAddress((void**)&p_h1,  g_h1);
    cudaGetSymbolAddress((void**)&p_h2,  g_h2);
    cudaGetSymbolAddress((void**)&p_w2t, g_w2t);
    cudaGetSymbolAddress((void**)&p_w3t, g_w3t);
    cudaGetSymbolAddress((void**)&p_w,   g_w);
    cudaGetSymbolAddress((void**)&p_b3p, g_b3p);

    cudaFuncSetAttribute(k_gemm_mma, cudaFuncAttributeMaxDynamicSharedMemorySize, GEMM_SMEM);

    k_zero_agg<<<(NNODES * 3 + 255) / 256, 256>>>();
    k_count  <<<NB, 1024>>>(src, dst, E);
    k_scan   <<<1, 1024>>>(NB);
    k_scatter<<<NB, 1024>>>(src, dst, ea, E);
    k_convW2 <<<(HID * HID + 255) / 256, 256>>>(mW2);
    k_convW3 <<<(MSGP * HID + 255) / 256, 256>>>(mW3, mb3);

    k_layer1 <<<esel / L1_EPB, 256>>>(mW1, mb1, esel);

    // GEMM2: h2 = leaky(h1 @ W2 + b2), fp16 out
    dim3 g2(HID / 128, esel / 128);
    k_gemm_mma<<<g2, 256, GEMM_SMEM>>>(p_h1, p_w2t, mb2, nullptr, p_h2, HID, HID, 1);
    // GEMM3: w = h2 @ W3p + b3p, fp32 out
    dim3 g3(MSGP / 128, esel / 128);
    k_gemm_mma<<<g3, 256, GEMM_SMEM>>>(p_h2, p_w3t, p_b3p, p_w, nullptr, HID, MSGP, 0);

    k_msg_scatter<<<(esel * 32 + 255) / 256, 256>>>(esel);

    k_update<<<(NNODES + 127) / 128, 128>>>(x, ln_g, ln_b, uW1, ub1, uW2, ub2,
                                            uW3, ub3, (float*)d_out);
}